// round 1
// baseline (speedup 1.0000x reference)
#include <cuda_runtime.h>

// StrictProjectionBlock: 4M independent 3x3 fp32 matrices.
//   Q = X / ||X||_F
//   repeat 4x:  N = Q^T Q;  P = 0.5*Q*N;  Q = 2Q + P*N - 3P
//
// One matrix per thread, all-register math. Shared-memory staging turns the
// 36-byte-per-matrix layout into fully-coalesced float4 gmem traffic;
// stride-9 smem access is bank-conflict-free (gcd(9,32)=1).

constexpr int MPB = 256;              // matrices per block
constexpr int THREADS = 256;
constexpr int FLOATS_PER_BLOCK = MPB * 9;            // 2304
constexpr int VEC4_PER_BLOCK = FLOATS_PER_BLOCK / 4; // 576

__global__ void __launch_bounds__(THREADS, 1)
strict_projection_kernel(const float* __restrict__ in,
                         float* __restrict__ out,
                         int n_mat)
{
    __shared__ float smem[FLOATS_PER_BLOCK];

    const int base = blockIdx.x * MPB;
    const size_t fbase = (size_t)base * 9;
    const int tid = threadIdx.x;

    const bool full_block = (base + MPB) <= n_mat;

    // ---- Load: gmem -> smem, coalesced float4 ----
    if (full_block) {
        // fbase*4 bytes = blockIdx * 9216, multiple of 16 -> float4-aligned.
        const float4* in4 = reinterpret_cast<const float4*>(in + fbase);
        float4* s4 = reinterpret_cast<float4*>(smem);
        #pragma unroll
        for (int i = tid; i < VEC4_PER_BLOCK; i += THREADS)
            s4[i] = in4[i];
    } else {
        const int nfl = (n_mat - base) * 9;
        for (int i = tid; i < nfl; i += THREADS)
            smem[i] = in[fbase + i];
    }
    __syncthreads();

    const int m = base + tid;
    const bool active = (m < n_mat);

    float q0, q1, q2, q3, q4, q5, q6, q7, q8;

    if (active) {
        const float* sm = smem + tid * 9;
        q0 = sm[0]; q1 = sm[1]; q2 = sm[2];
        q3 = sm[3]; q4 = sm[4]; q5 = sm[5];
        q6 = sm[6]; q7 = sm[7]; q8 = sm[8];

        // Frobenius normalize
        float ss = q0*q0 + q1*q1 + q2*q2
                 + q3*q3 + q4*q4 + q5*q5
                 + q6*q6 + q7*q7 + q8*q8;
        float inv = rsqrtf(ss);
        q0 *= inv; q1 *= inv; q2 *= inv;
        q3 *= inv; q4 *= inv; q5 *= inv;
        q6 *= inv; q7 *= inv; q8 *= inv;

        #pragma unroll
        for (int layer = 0; layer < 4; ++layer) {
            // N = Q^T Q (symmetric: 6 unique entries)
            float n00 = q0*q0 + q3*q3 + q6*q6;
            float n01 = q0*q1 + q3*q4 + q6*q7;
            float n02 = q0*q2 + q3*q5 + q6*q8;
            float n11 = q1*q1 + q4*q4 + q7*q7;
            float n12 = q1*q2 + q4*q5 + q7*q8;
            float n22 = q2*q2 + q5*q5 + q8*q8;

            // P = 0.5 * Q * N
            float p0 = 0.5f * (q0*n00 + q1*n01 + q2*n02);
            float p1 = 0.5f * (q0*n01 + q1*n11 + q2*n12);
            float p2 = 0.5f * (q0*n02 + q1*n12 + q2*n22);
            float p3 = 0.5f * (q3*n00 + q4*n01 + q5*n02);
            float p4 = 0.5f * (q3*n01 + q4*n11 + q5*n12);
            float p5 = 0.5f * (q3*n02 + q4*n12 + q5*n22);
            float p6 = 0.5f * (q6*n00 + q7*n01 + q8*n02);
            float p7 = 0.5f * (q6*n01 + q7*n11 + q8*n12);
            float p8 = 0.5f * (q6*n02 + q7*n12 + q8*n22);

            // Q = 2Q + P*N - 3P
            q0 = 2.0f*q0 + (p0*n00 + p1*n01 + p2*n02) - 3.0f*p0;
            q1 = 2.0f*q1 + (p0*n01 + p1*n11 + p2*n12) - 3.0f*p1;
            q2 = 2.0f*q2 + (p0*n02 + p1*n12 + p2*n22) - 3.0f*p2;
            q3 = 2.0f*q3 + (p3*n00 + p4*n01 + p5*n02) - 3.0f*p3;
            q4 = 2.0f*q4 + (p3*n01 + p4*n11 + p5*n12) - 3.0f*p4;
            q5 = 2.0f*q5 + (p3*n02 + p4*n12 + p5*n22) - 3.0f*p5;
            q6 = 2.0f*q6 + (p6*n00 + p7*n01 + p8*n02) - 3.0f*p6;
            q7 = 2.0f*q7 + (p6*n01 + p7*n11 + p8*n12) - 3.0f*p7;
            q8 = 2.0f*q8 + (p6*n02 + p7*n12 + p8*n22) - 3.0f*p8;
        }
    }
    __syncthreads();   // smem reused for output staging

    if (active) {
        float* sm = smem + tid * 9;
        sm[0] = q0; sm[1] = q1; sm[2] = q2;
        sm[3] = q3; sm[4] = q4; sm[5] = q5;
        sm[6] = q6; sm[7] = q7; sm[8] = q8;
    }
    __syncthreads();

    // ---- Store: smem -> gmem, coalesced float4 ----
    if (full_block) {
        float4* out4 = reinterpret_cast<float4*>(out + fbase);
        const float4* s4 = reinterpret_cast<const float4*>(smem);
        #pragma unroll
        for (int i = tid; i < VEC4_PER_BLOCK; i += THREADS)
            out4[i] = s4[i];
    } else {
        const int nfl = (n_mat - base) * 9;
        for (int i = tid; i < nfl; i += THREADS)
            out[fbase + i] = smem[i];
    }
}

extern "C" void kernel_launch(void* const* d_in, const int* in_sizes, int n_in,
                              void* d_out, int out_size)
{
    const float* x = (const float*)d_in[0];
    float* out = (float*)d_out;
    const int n_mat = in_sizes[0] / 9;          // 4,000,000
    const int grid = (n_mat + MPB - 1) / MPB;   // 15,625
    strict_projection_kernel<<<grid, THREADS>>>(x, out, n_mat);
}

// round 2
// speedup vs baseline: 1.2750x; 1.2750x over previous
#include <cuda_runtime.h>

// StrictProjectionBlock: 4M independent 3x3 fp32 matrices.
//   Q = X/||X||_F ; 4x:  Q <- Q * (2I - 1.5*N + 0.5*N^2),  N = Q^T Q (symmetric)
//
// Two matrices per thread, all math in packed fp32x2 (fma.rn.f32x2 — double
// rate on sm_103a, ptxas never auto-emits it). Shared-memory staging keeps
// gmem traffic fully-coalesced float4.

using u64 = unsigned long long;

__device__ __forceinline__ u64 pk2(float lo, float hi) {
    u64 r; asm("mov.b64 %0, {%1,%2};" : "=l"(r) : "f"(lo), "f"(hi)); return r;
}
__device__ __forceinline__ void upk2(u64 v, float& lo, float& hi) {
    asm("mov.b64 {%0,%1}, %2;" : "=f"(lo), "=f"(hi) : "l"(v));
}
__device__ __forceinline__ u64 fma2(u64 a, u64 b, u64 c) {
    u64 d; asm("fma.rn.f32x2 %0, %1, %2, %3;" : "=l"(d) : "l"(a), "l"(b), "l"(c)); return d;
}
__device__ __forceinline__ u64 mul2(u64 a, u64 b) {
    u64 d; asm("mul.rn.f32x2 %0, %1, %2;" : "=l"(d) : "l"(a), "l"(b)); return d;
}

constexpr int THREADS = 256;
constexpr int MPT = 2;                    // matrices per thread
constexpr int MPB = THREADS * MPT;        // 512 matrices per block
constexpr int FPB = MPB * 9;              // 4608 floats
constexpr int V4  = FPB / 4;              // 1152 float4

// packed constants (both lanes identical)
constexpr u64 C_HALF = 0x3F0000003F000000ULL;  // (0.5, 0.5)
constexpr u64 C_M3H  = 0xBFC00000BFC00000ULL;  // (-1.5, -1.5)
constexpr u64 C_TWO  = 0x4000000040000000ULL;  // (2.0, 2.0)

__global__ void __launch_bounds__(THREADS, 4)
strict_projection_kernel(const float* __restrict__ in,
                         float* __restrict__ out,
                         int n_mat)
{
    __shared__ float smem[FPB];

    const int tid  = threadIdx.x;
    const int base = blockIdx.x * MPB;
    const size_t fbase = (size_t)base * 9;
    const bool full_block = (base + MPB) <= n_mat;

    // ---- Load: gmem -> smem, coalesced float4 ----
    if (full_block) {
        const float4* in4 = reinterpret_cast<const float4*>(in + fbase);
        float4* s4 = reinterpret_cast<float4*>(smem);
        #pragma unroll
        for (int i = tid; i < V4; i += THREADS) s4[i] = in4[i];
    } else {
        const int nfl = (n_mat - base) * 9;
        for (int i = tid; i < nfl; i += THREADS) smem[i] = in[fbase + i];
    }
    __syncthreads();

    const int ma = base + 2 * tid;        // first matrix (lane lo)
    const int mb = ma + 1;                // second matrix (lane hi)
    const bool va = (ma < n_mat);
    const bool vb = (mb < n_mat);

    const float* A = smem + (2 * tid) * 9;
    const float* B = vb ? (A + 9) : A;    // duplicate A if B invalid

    u64 q0, q1, q2, q3, q4, q5, q6, q7, q8;
    q0 = pk2(A[0], B[0]); q1 = pk2(A[1], B[1]); q2 = pk2(A[2], B[2]);
    q3 = pk2(A[3], B[3]); q4 = pk2(A[4], B[4]); q5 = pk2(A[5], B[5]);
    q6 = pk2(A[6], B[6]); q7 = pk2(A[7], B[7]); q8 = pk2(A[8], B[8]);

    // Frobenius normalize (per lane)
    u64 ss = mul2(q0, q0);
    ss = fma2(q1, q1, ss); ss = fma2(q2, q2, ss);
    ss = fma2(q3, q3, ss); ss = fma2(q4, q4, ss);
    ss = fma2(q5, q5, ss); ss = fma2(q6, q6, ss);
    ss = fma2(q7, q7, ss); ss = fma2(q8, q8, ss);
    float sa, sb; upk2(ss, sa, sb);
    const u64 inv = pk2(rsqrtf(sa), rsqrtf(sb));
    q0 = mul2(q0, inv); q1 = mul2(q1, inv); q2 = mul2(q2, inv);
    q3 = mul2(q3, inv); q4 = mul2(q4, inv); q5 = mul2(q5, inv);
    q6 = mul2(q6, inv); q7 = mul2(q7, inv); q8 = mul2(q8, inv);

    #pragma unroll
    for (int layer = 0; layer < 4; ++layer) {
        // N = Q^T Q  (symmetric, 6 unique)
        u64 n00 = fma2(q6, q6, fma2(q3, q3, mul2(q0, q0)));
        u64 n01 = fma2(q6, q7, fma2(q3, q4, mul2(q0, q1)));
        u64 n02 = fma2(q6, q8, fma2(q3, q5, mul2(q0, q2)));
        u64 n11 = fma2(q7, q7, fma2(q4, q4, mul2(q1, q1)));
        u64 n12 = fma2(q7, q8, fma2(q4, q5, mul2(q1, q2)));
        u64 n22 = fma2(q8, q8, fma2(q5, q5, mul2(q2, q2)));

        // T = N^2 (symmetric)
        u64 t00 = fma2(n02, n02, fma2(n01, n01, mul2(n00, n00)));
        u64 t01 = fma2(n02, n12, fma2(n01, n11, mul2(n00, n01)));
        u64 t02 = fma2(n02, n22, fma2(n01, n12, mul2(n00, n02)));
        u64 t11 = fma2(n12, n12, fma2(n11, n11, mul2(n01, n01)));
        u64 t12 = fma2(n12, n22, fma2(n11, n12, mul2(n01, n02)));
        u64 t22 = fma2(n22, n22, fma2(n12, n12, mul2(n02, n02)));

        // M = 2I - 1.5*N + 0.5*T  (symmetric)
        u64 m00 = fma2(C_HALF, t00, fma2(C_M3H, n00, C_TWO));
        u64 m01 = fma2(C_HALF, t01, mul2(C_M3H, n01));
        u64 m02 = fma2(C_HALF, t02, mul2(C_M3H, n02));
        u64 m11 = fma2(C_HALF, t11, fma2(C_M3H, n11, C_TWO));
        u64 m12 = fma2(C_HALF, t12, mul2(C_M3H, n12));
        u64 m22 = fma2(C_HALF, t22, fma2(C_M3H, n22, C_TWO));

        // Q <- Q * M
        u64 r0 = fma2(q2, m02, fma2(q1, m01, mul2(q0, m00)));
        u64 r1 = fma2(q2, m12, fma2(q1, m11, mul2(q0, m01)));
        u64 r2 = fma2(q2, m22, fma2(q1, m12, mul2(q0, m02)));
        u64 r3 = fma2(q5, m02, fma2(q4, m01, mul2(q3, m00)));
        u64 r4 = fma2(q5, m12, fma2(q4, m11, mul2(q3, m01)));
        u64 r5 = fma2(q5, m22, fma2(q4, m12, mul2(q3, m02)));
        u64 r6 = fma2(q8, m02, fma2(q7, m01, mul2(q6, m00)));
        u64 r7 = fma2(q8, m12, fma2(q7, m11, mul2(q6, m01)));
        u64 r8 = fma2(q8, m22, fma2(q7, m12, mul2(q6, m02)));
        q0 = r0; q1 = r1; q2 = r2;
        q3 = r3; q4 = r4; q5 = r5;
        q6 = r6; q7 = r7; q8 = r8;
    }
    __syncthreads();   // smem reuse for output staging

    {
        float* sa_ = smem + (2 * tid) * 9;
        float* sb_ = sa_ + 9;
        float a0, b0;
        if (va) {
            upk2(q0, a0, b0); sa_[0] = a0; if (vb) sb_[0] = b0;
            upk2(q1, a0, b0); sa_[1] = a0; if (vb) sb_[1] = b0;
            upk2(q2, a0, b0); sa_[2] = a0; if (vb) sb_[2] = b0;
            upk2(q3, a0, b0); sa_[3] = a0; if (vb) sb_[3] = b0;
            upk2(q4, a0, b0); sa_[4] = a0; if (vb) sb_[4] = b0;
            upk2(q5, a0, b0); sa_[5] = a0; if (vb) sb_[5] = b0;
            upk2(q6, a0, b0); sa_[6] = a0; if (vb) sb_[6] = b0;
            upk2(q7, a0, b0); sa_[7] = a0; if (vb) sb_[7] = b0;
            upk2(q8, a0, b0); sa_[8] = a0; if (vb) sb_[8] = b0;
        }
    }
    __syncthreads();

    // ---- Store: smem -> gmem, coalesced float4 ----
    if (full_block) {
        float4* out4 = reinterpret_cast<float4*>(out + fbase);
        const float4* s4 = reinterpret_cast<const float4*>(smem);
        #pragma unroll
        for (int i = tid; i < V4; i += THREADS) out4[i] = s4[i];
    } else {
        const int nfl = (n_mat - base) * 9;
        for (int i = tid; i < nfl; i += THREADS) out[fbase + i] = smem[i];
    }
}

extern "C" void kernel_launch(void* const* d_in, const int* in_sizes, int n_in,
                              void* d_out, int out_size)
{
    const float* x = (const float*)d_in[0];
    float* out = (float*)d_out;
    const int n_mat = in_sizes[0] / 9;               // 4,000,000
    const int grid = (n_mat + MPB - 1) / MPB;        // 7,813
    strict_projection_kernel<<<grid, THREADS>>>(x, out, n_mat);
}

// round 3
// speedup vs baseline: 1.4795x; 1.1604x over previous
#include <cuda_runtime.h>
#include <cstdint>

// StrictProjectionBlock: 4M independent 3x3 fp32 matrices.
//   Q = X/||X||_F ; 4x:  Q <- Q * (0.5*(N-1.5I)^2 + 0.875I),  N = Q^T Q
//   (identical to 2I - 1.5N + 0.5N^2)
//
// Persistent grid-stride CTAs, double-buffered smem tiles filled via
// cp.async.cg (prefetch tile t+1 overlaps compute of tile t).
// Two matrices per thread, all math in packed fp32x2 (double-rate on sm_103a).

using u64 = unsigned long long;

__device__ __forceinline__ u64 pk2(float lo, float hi) {
    u64 r; asm("mov.b64 %0, {%1,%2};" : "=l"(r) : "f"(lo), "f"(hi)); return r;
}
__device__ __forceinline__ void upk2(u64 v, float& lo, float& hi) {
    asm("mov.b64 {%0,%1}, %2;" : "=f"(lo), "=f"(hi) : "l"(v));
}
__device__ __forceinline__ u64 fma2(u64 a, u64 b, u64 c) {
    u64 d; asm("fma.rn.f32x2 %0, %1, %2, %3;" : "=l"(d) : "l"(a), "l"(b), "l"(c)); return d;
}
__device__ __forceinline__ u64 mul2(u64 a, u64 b) {
    u64 d; asm("mul.rn.f32x2 %0, %1, %2;" : "=l"(d) : "l"(a), "l"(b)); return d;
}
__device__ __forceinline__ u64 add2(u64 a, u64 b) {
    u64 d; asm("add.rn.f32x2 %0, %1, %2;" : "=l"(d) : "l"(a), "l"(b)); return d;
}

__device__ __forceinline__ uint32_t smem_u32(const void* p) {
    uint32_t a;
    asm("{ .reg .u64 t; cvta.to.shared.u64 t, %1; cvt.u32.u64 %0, t; }" : "=r"(a) : "l"(p));
    return a;
}
__device__ __forceinline__ void cpa16(uint32_t s, const void* g) {
    asm volatile("cp.async.cg.shared.global [%0], [%1], 16;" :: "r"(s), "l"(g));
}
__device__ __forceinline__ void cpa4(uint32_t s, const void* g) {
    asm volatile("cp.async.ca.shared.global [%0], [%1], 4;" :: "r"(s), "l"(g));
}
__device__ __forceinline__ void cpa_commit() { asm volatile("cp.async.commit_group;"); }
__device__ __forceinline__ void cpa_wait1()  { asm volatile("cp.async.wait_group 1;"); }
__device__ __forceinline__ void cpa_wait0()  { asm volatile("cp.async.wait_group 0;"); }

constexpr int THREADS = 256;
constexpr int MPT = 2;                    // matrices per thread (packed lanes)
constexpr int MPB = THREADS * MPT;        // 512 matrices per tile
constexpr int FPB = MPB * 9;              // 4608 floats per tile
constexpr int V4  = FPB / 4;              // 1152 float4 per tile

// packed fp32x2 constants (both lanes identical)
constexpr u64 C_HALF = 0x3F0000003F000000ULL;  // ( 0.5  , 0.5  )
constexpr u64 C_M15  = 0xBFC00000BFC00000ULL;  // (-1.5  ,-1.5  )
constexpr u64 C_7o8  = 0x3F6000003F600000ULL;  // ( 0.875, 0.875)

__global__ void __launch_bounds__(THREADS, 4)
strict_projection_kernel(const float* __restrict__ in,
                         float* __restrict__ out,
                         int n_mat, int n_tiles)
{
    __shared__ float smem[2][FPB];

    const int tid = threadIdx.x;
    const uint32_t sb0 = smem_u32(&smem[0][0]);
    const uint32_t sb1 = smem_u32(&smem[1][0]);

    const int stride = gridDim.x;
    const int t0 = blockIdx.x;
    if (t0 >= n_tiles) return;

    // ---- prefetch helper: tile -> smem buffer via cp.async ----
    auto prefetch = [&](int tile, uint32_t sbase) {
        const int base = tile * MPB;
        const int nfl = (min(n_mat, base + MPB) - base) * 9;
        const int nv4 = nfl >> 2, rem = nfl & 3;
        const float* g = in + (size_t)base * 9;   // byte offset multiple of 16
        for (int i = tid; i < nv4; i += THREADS)
            cpa16(sbase + (uint32_t)i * 16u, g + (size_t)i * 4);
        for (int i = tid; i < rem; i += THREADS)
            cpa4(sbase + (uint32_t)(nv4 * 4 + i) * 4u, g + nv4 * 4 + i);
    };

    prefetch(t0, sb0);
    cpa_commit();

    int buf = 0;
    for (int t = t0; t < n_tiles; t += stride, buf ^= 1) {
        const int tn = t + stride;
        if (tn < n_tiles) {
            prefetch(tn, buf ? sb0 : sb1);
            cpa_commit();
            cpa_wait1();     // tile t's group complete
        } else {
            cpa_wait0();
        }
        __syncthreads();

        const int base = t * MPB;
        const int ma = base + 2 * tid;
        const bool va = (ma < n_mat);
        const bool vb = (ma + 1 < n_mat);

        float* A = &smem[buf][2 * tid * 9];
        const float* B = vb ? (A + 9) : A;

        u64 q0 = pk2(A[0], B[0]), q1 = pk2(A[1], B[1]), q2 = pk2(A[2], B[2]);
        u64 q3 = pk2(A[3], B[3]), q4 = pk2(A[4], B[4]), q5 = pk2(A[5], B[5]);
        u64 q6 = pk2(A[6], B[6]), q7 = pk2(A[7], B[7]), q8 = pk2(A[8], B[8]);

        // Frobenius normalize
        u64 ss = mul2(q0, q0);
        ss = fma2(q1, q1, ss); ss = fma2(q2, q2, ss);
        ss = fma2(q3, q3, ss); ss = fma2(q4, q4, ss);
        ss = fma2(q5, q5, ss); ss = fma2(q6, q6, ss);
        ss = fma2(q7, q7, ss); ss = fma2(q8, q8, ss);
        float sa, sbf; upk2(ss, sa, sbf);
        const u64 inv = pk2(rsqrtf(sa), rsqrtf(sbf));
        q0 = mul2(q0, inv); q1 = mul2(q1, inv); q2 = mul2(q2, inv);
        q3 = mul2(q3, inv); q4 = mul2(q4, inv); q5 = mul2(q5, inv);
        q6 = mul2(q6, inv); q7 = mul2(q7, inv); q8 = mul2(q8, inv);

        #pragma unroll
        for (int layer = 0; layer < 4; ++layer) {
            // N = Q^T Q (symmetric)
            u64 n00 = fma2(q6, q6, fma2(q3, q3, mul2(q0, q0)));
            u64 n01 = fma2(q6, q7, fma2(q3, q4, mul2(q0, q1)));
            u64 n02 = fma2(q6, q8, fma2(q3, q5, mul2(q0, q2)));
            u64 n11 = fma2(q7, q7, fma2(q4, q4, mul2(q1, q1)));
            u64 n12 = fma2(q7, q8, fma2(q4, q5, mul2(q1, q2)));
            u64 n22 = fma2(q8, q8, fma2(q5, q5, mul2(q2, q2)));

            // S = N - 1.5I (diagonal only; off-diag entries are n01,n02,n12)
            u64 s00 = add2(n00, C_M15);
            u64 s11 = add2(n11, C_M15);
            u64 s22 = add2(n22, C_M15);

            // T = S^2 (symmetric)
            u64 t00 = fma2(n02, n02, fma2(n01, n01, mul2(s00, s00)));
            u64 t01 = fma2(n02, n12, fma2(n01, s11, mul2(s00, n01)));
            u64 t02 = fma2(n02, s22, fma2(n01, n12, mul2(s00, n02)));
            u64 t11 = fma2(n12, n12, fma2(s11, s11, mul2(n01, n01)));
            u64 t12 = fma2(n12, s22, fma2(s11, n12, mul2(n01, n02)));
            u64 t22 = fma2(s22, s22, fma2(n12, n12, mul2(n02, n02)));

            // M = 0.5*T + 0.875*I  ==  2I - 1.5N + 0.5N^2
            u64 m00 = fma2(C_HALF, t00, C_7o8);
            u64 m01 = mul2(C_HALF, t01);
            u64 m02 = mul2(C_HALF, t02);
            u64 m11 = fma2(C_HALF, t11, C_7o8);
            u64 m12 = mul2(C_HALF, t12);
            u64 m22 = fma2(C_HALF, t22, C_7o8);

            // Q <- Q * M
            u64 r0 = fma2(q2, m02, fma2(q1, m01, mul2(q0, m00)));
            u64 r1 = fma2(q2, m12, fma2(q1, m11, mul2(q0, m01)));
            u64 r2 = fma2(q2, m22, fma2(q1, m12, mul2(q0, m02)));
            u64 r3 = fma2(q5, m02, fma2(q4, m01, mul2(q3, m00)));
            u64 r4 = fma2(q5, m12, fma2(q4, m11, mul2(q3, m01)));
            u64 r5 = fma2(q5, m22, fma2(q4, m12, mul2(q3, m02)));
            u64 r6 = fma2(q8, m02, fma2(q7, m01, mul2(q6, m00)));
            u64 r7 = fma2(q8, m12, fma2(q7, m11, mul2(q6, m01)));
            u64 r8 = fma2(q8, m22, fma2(q7, m12, mul2(q6, m02)));
            q0 = r0; q1 = r1; q2 = r2;
            q3 = r3; q4 = r4; q5 = r5;
            q6 = r6; q7 = r7; q8 = r8;
        }

        // write results back into own smem region (only this thread read it)
        if (va) {
            float* sa_ = A;
            float* sb_ = A + 9;
            float x, y;
            upk2(q0, x, y); sa_[0] = x; if (vb) sb_[0] = y;
            upk2(q1, x, y); sa_[1] = x; if (vb) sb_[1] = y;
            upk2(q2, x, y); sa_[2] = x; if (vb) sb_[2] = y;
            upk2(q3, x, y); sa_[3] = x; if (vb) sb_[3] = y;
            upk2(q4, x, y); sa_[4] = x; if (vb) sb_[4] = y;
            upk2(q5, x, y); sa_[5] = x; if (vb) sb_[5] = y;
            upk2(q6, x, y); sa_[6] = x; if (vb) sb_[6] = y;
            upk2(q7, x, y); sa_[7] = x; if (vb) sb_[7] = y;
            upk2(q8, x, y); sa_[8] = x; if (vb) sb_[8] = y;
        }
        __syncthreads();

        // ---- store: smem -> gmem, coalesced float4 ----
        {
            const int nfl = (min(n_mat, base + MPB) - base) * 9;
            const int nv4 = nfl >> 2, rem = nfl & 3;
            float4* o4 = reinterpret_cast<float4*>(out + (size_t)base * 9);
            const float4* s4 = reinterpret_cast<const float4*>(&smem[buf][0]);
            for (int i = tid; i < nv4; i += THREADS) o4[i] = s4[i];
            for (int i = tid; i < rem; i += THREADS)
                out[(size_t)base * 9 + nv4 * 4 + i] = smem[buf][nv4 * 4 + i];
        }
        __syncthreads();  // all store-phase smem reads done before next
                          // iteration's cp.async overwrites this buffer
    }
}

extern "C" void kernel_launch(void* const* d_in, const int* in_sizes, int n_in,
                              void* d_out, int out_size)
{
    const float* x = (const float*)d_in[0];
    float* out = (float*)d_out;
    const int n_mat = in_sizes[0] / 9;                    // 4,000,000
    const int n_tiles = (n_mat + MPB - 1) / MPB;          // 7,813
    int grid = 152 * 4;                                   // persistent: 4 CTAs/SM
    if (grid > n_tiles) grid = n_tiles;
    strict_projection_kernel<<<grid, THREADS>>>(x, out, n_mat, n_tiles);
}

// round 4
// speedup vs baseline: 1.6577x; 1.1204x over previous
#include <cuda_runtime.h>
#include <cstdint>

// StrictProjectionBlock: 4M independent 3x3 fp32 matrices.
//   Q = X/||X||_F ; 4x:  Q <- Q * (0.5*(N-1.5I)^2 + 0.875I),  N = Q^T Q
//
// Warp-autonomous pipelines: each warp owns a private double-buffered smem
// slice, streams 64-matrix tiles via cp.async.cg, computes 2 matrices/thread
// in packed fp32x2 (double-rate on sm_103a), and copies out coalesced.
// No block barriers anywhere -> warps drift out of phase and FMA/LSU overlap.

using u64 = unsigned long long;

__device__ __forceinline__ u64 pk2(float lo, float hi) {
    u64 r; asm("mov.b64 %0, {%1,%2};" : "=l"(r) : "f"(lo), "f"(hi)); return r;
}
__device__ __forceinline__ void upk2(u64 v, float& lo, float& hi) {
    asm("mov.b64 {%0,%1}, %2;" : "=f"(lo), "=f"(hi) : "l"(v));
}
__device__ __forceinline__ float lo2(u64 v) { float a, b; upk2(v, a, b); return a; }
__device__ __forceinline__ float hi2(u64 v) { float a, b; upk2(v, a, b); return b; }
__device__ __forceinline__ u64 fma2(u64 a, u64 b, u64 c) {
    u64 d; asm("fma.rn.f32x2 %0, %1, %2, %3;" : "=l"(d) : "l"(a), "l"(b), "l"(c)); return d;
}
__device__ __forceinline__ u64 mul2(u64 a, u64 b) {
    u64 d; asm("mul.rn.f32x2 %0, %1, %2;" : "=l"(d) : "l"(a), "l"(b)); return d;
}
__device__ __forceinline__ u64 add2(u64 a, u64 b) {
    u64 d; asm("add.rn.f32x2 %0, %1, %2;" : "=l"(d) : "l"(a), "l"(b)); return d;
}
__device__ __forceinline__ uint32_t smem_u32(const void* p) {
    uint32_t a;
    asm("{ .reg .u64 t; cvta.to.shared.u64 t, %1; cvt.u32.u64 %0, t; }" : "=r"(a) : "l"(p));
    return a;
}
__device__ __forceinline__ void cpa16(uint32_t s, const void* g) {
    asm volatile("cp.async.cg.shared.global [%0], [%1], 16;" :: "r"(s), "l"(g));
}
__device__ __forceinline__ void cpa_commit() { asm volatile("cp.async.commit_group;"); }
__device__ __forceinline__ void cpa_wait1()  { asm volatile("cp.async.wait_group 1;"); }
__device__ __forceinline__ void cpa_wait0()  { asm volatile("cp.async.wait_group 0;"); }

constexpr int THREADS = 256;
constexpr int WARPS   = THREADS / 32;     // 8
constexpr int WMT     = 64;               // matrices per warp-tile (2/thread)
constexpr int WFL     = WMT * 9;          // 576 floats = 2304 bytes per tile
constexpr int WV4     = WFL / 4;          // 144 float4

// packed fp32x2 constants (both lanes identical)
constexpr u64 C_HALF = 0x3F0000003F000000ULL;  // ( 0.5  , 0.5  )
constexpr u64 C_M15  = 0xBFC00000BFC00000ULL;  // (-1.5  ,-1.5  )
constexpr u64 C_7o8  = 0x3F6000003F600000ULL;  // ( 0.875, 0.875)

// scalar fallback for remainder matrices (n_mat % 64 != 0; unused for 4M)
__device__ void project1(float* q) {
    float ss = 0.f;
    #pragma unroll
    for (int i = 0; i < 9; i++) ss += q[i] * q[i];
    float inv = rsqrtf(ss);
    #pragma unroll
    for (int i = 0; i < 9; i++) q[i] *= inv;
    #pragma unroll
    for (int l = 0; l < 4; l++) {
        float n00 = q[0]*q[0]+q[3]*q[3]+q[6]*q[6];
        float n01 = q[0]*q[1]+q[3]*q[4]+q[6]*q[7];
        float n02 = q[0]*q[2]+q[3]*q[5]+q[6]*q[8];
        float n11 = q[1]*q[1]+q[4]*q[4]+q[7]*q[7];
        float n12 = q[1]*q[2]+q[4]*q[5]+q[7]*q[8];
        float n22 = q[2]*q[2]+q[5]*q[5]+q[8]*q[8];
        float s00 = n00-1.5f, s11 = n11-1.5f, s22 = n22-1.5f;
        float m00 = 0.5f*(s00*s00+n01*n01+n02*n02)+0.875f;
        float m01 = 0.5f*(s00*n01+n01*s11+n02*n12);
        float m02 = 0.5f*(s00*n02+n01*n12+n02*s22);
        float m11 = 0.5f*(n01*n01+s11*s11+n12*n12)+0.875f;
        float m12 = 0.5f*(n01*n02+s11*n12+n12*s22);
        float m22 = 0.5f*(n02*n02+n12*n12+s22*s22)+0.875f;
        float r0 = q[0]*m00+q[1]*m01+q[2]*m02;
        float r1 = q[0]*m01+q[1]*m11+q[2]*m12;
        float r2 = q[0]*m02+q[1]*m12+q[2]*m22;
        float r3 = q[3]*m00+q[4]*m01+q[5]*m02;
        float r4 = q[3]*m01+q[4]*m11+q[5]*m12;
        float r5 = q[3]*m02+q[4]*m12+q[5]*m22;
        float r6 = q[6]*m00+q[7]*m01+q[8]*m02;
        float r7 = q[6]*m01+q[7]*m11+q[8]*m12;
        float r8 = q[6]*m02+q[7]*m12+q[8]*m22;
        q[0]=r0; q[1]=r1; q[2]=r2; q[3]=r3; q[4]=r4;
        q[5]=r5; q[6]=r6; q[7]=r7; q[8]=r8;
    }
}

__global__ void __launch_bounds__(THREADS, 4)
strict_projection_kernel(const float* __restrict__ in,
                         float* __restrict__ out,
                         int n_mat, int n_wt)
{
    __shared__ float smem[WARPS][2][WFL];

    const int lane = threadIdx.x & 31;
    const int wid  = threadIdx.x >> 5;

    // ---- remainder matrices (n_mat % 64), handled by block 0 / warp 0 ----
    if (blockIdx.x == 0 && wid == 0) {
        const int rem_base = n_wt * WMT;
        const int m = rem_base + lane;
        if (m < n_mat) {
            float q[9];
            #pragma unroll
            for (int i = 0; i < 9; i++) q[i] = in[(size_t)m * 9 + i];
            project1(q);
            #pragma unroll
            for (int i = 0; i < 9; i++) out[(size_t)m * 9 + i] = q[i];
        }
        const int m2 = rem_base + 32 + lane;
        if (m2 < n_mat) {
            float q[9];
            #pragma unroll
            for (int i = 0; i < 9; i++) q[i] = in[(size_t)m2 * 9 + i];
            project1(q);
            #pragma unroll
            for (int i = 0; i < 9; i++) out[(size_t)m2 * 9 + i] = q[i];
        }
    }

    const int wgid    = blockIdx.x * WARPS + wid;
    const int wstride = gridDim.x * WARPS;
    if (wgid >= n_wt) return;

    const uint32_t sb[2] = { smem_u32(&smem[wid][0][0]), smem_u32(&smem[wid][1][0]) };

    // gmem pointers advance by wstride*WFL per iteration (no per-iter IMAD chains)
    const size_t step = (size_t)wstride * WFL;
    const float4* gin  = reinterpret_cast<const float4*>(in  + (size_t)wgid * WFL);
    float4*       gout = reinterpret_cast<float4*>(out + (size_t)wgid * WFL);
    const float4* gin_next = gin + step / 4;

    // prefetch: 144 float4 per tile, 32 lanes -> 4 full rounds + half round
    auto prefetch = [&](const float4* g, uint32_t s) {
        #pragma unroll
        for (int k = 0; k < 4; k++)
            cpa16(s + (uint32_t)(lane + 32 * k) * 16u, g + lane + 32 * k);
        if (lane < 16)
            cpa16(s + (uint32_t)(128 + lane) * 16u, g + 128 + lane);
    };

    prefetch(gin, sb[0]);
    cpa_commit();

    int buf = 0;
    for (int t = wgid; t < n_wt; t += wstride, buf ^= 1) {
        const bool have_next = (t + wstride) < n_wt;
        if (have_next) {
            prefetch(gin_next, sb[buf ^ 1]);
            cpa_commit();
            cpa_wait1();
        } else {
            cpa_wait0();
        }
        __syncwarp();   // all lanes' groups drained -> whole tile visible

        // ---- load own 18 floats as 9 x LDS.64, repack to (A[i],B[i]) pairs ----
        const u64* a8 = reinterpret_cast<const u64*>(&smem[wid][buf][lane * 18]);
        u64 p0 = a8[0], p1 = a8[1], p2 = a8[2], p3 = a8[3], p4 = a8[4];
        u64 p5 = a8[5], p6 = a8[6], p7 = a8[7], p8 = a8[8];

        u64 q0 = pk2(lo2(p0), hi2(p4));
        u64 q1 = pk2(hi2(p0), lo2(p5));
        u64 q2 = pk2(lo2(p1), hi2(p5));
        u64 q3 = pk2(hi2(p1), lo2(p6));
        u64 q4 = pk2(lo2(p2), hi2(p6));
        u64 q5 = pk2(hi2(p2), lo2(p7));
        u64 q6 = pk2(lo2(p3), hi2(p7));
        u64 q7 = pk2(hi2(p3), lo2(p8));
        u64 q8 = pk2(lo2(p4), hi2(p8));

        // ---- Frobenius normalize ----
        u64 ss = mul2(q0, q0);
        ss = fma2(q1, q1, ss); ss = fma2(q2, q2, ss);
        ss = fma2(q3, q3, ss); ss = fma2(q4, q4, ss);
        ss = fma2(q5, q5, ss); ss = fma2(q6, q6, ss);
        ss = fma2(q7, q7, ss); ss = fma2(q8, q8, ss);
        float sa, sbf; upk2(ss, sa, sbf);
        const u64 inv = pk2(rsqrtf(sa), rsqrtf(sbf));
        q0 = mul2(q0, inv); q1 = mul2(q1, inv); q2 = mul2(q2, inv);
        q3 = mul2(q3, inv); q4 = mul2(q4, inv); q5 = mul2(q5, inv);
        q6 = mul2(q6, inv); q7 = mul2(q7, inv); q8 = mul2(q8, inv);

        #pragma unroll
        for (int layer = 0; layer < 4; ++layer) {
            u64 n00 = fma2(q6, q6, fma2(q3, q3, mul2(q0, q0)));
            u64 n01 = fma2(q6, q7, fma2(q3, q4, mul2(q0, q1)));
            u64 n02 = fma2(q6, q8, fma2(q3, q5, mul2(q0, q2)));
            u64 n11 = fma2(q7, q7, fma2(q4, q4, mul2(q1, q1)));
            u64 n12 = fma2(q7, q8, fma2(q4, q5, mul2(q1, q2)));
            u64 n22 = fma2(q8, q8, fma2(q5, q5, mul2(q2, q2)));

            u64 s00 = add2(n00, C_M15);
            u64 s11 = add2(n11, C_M15);
            u64 s22 = add2(n22, C_M15);

            u64 t00 = fma2(n02, n02, fma2(n01, n01, mul2(s00, s00)));
            u64 t01 = fma2(n02, n12, fma2(n01, s11, mul2(s00, n01)));
            u64 t02 = fma2(n02, s22, fma2(n01, n12, mul2(s00, n02)));
            u64 t11 = fma2(n12, n12, fma2(s11, s11, mul2(n01, n01)));
            u64 t12 = fma2(n12, s22, fma2(s11, n12, mul2(n01, n02)));
            u64 t22 = fma2(s22, s22, fma2(n12, n12, mul2(n02, n02)));

            u64 m00 = fma2(C_HALF, t00, C_7o8);
            u64 m01 = mul2(C_HALF, t01);
            u64 m02 = mul2(C_HALF, t02);
            u64 m11 = fma2(C_HALF, t11, C_7o8);
            u64 m12 = mul2(C_HALF, t12);
            u64 m22 = fma2(C_HALF, t22, C_7o8);

            u64 r0 = fma2(q2, m02, fma2(q1, m01, mul2(q0, m00)));
            u64 r1 = fma2(q2, m12, fma2(q1, m11, mul2(q0, m01)));
            u64 r2 = fma2(q2, m22, fma2(q1, m12, mul2(q0, m02)));
            u64 r3 = fma2(q5, m02, fma2(q4, m01, mul2(q3, m00)));
            u64 r4 = fma2(q5, m12, fma2(q4, m11, mul2(q3, m01)));
            u64 r5 = fma2(q5, m22, fma2(q4, m12, mul2(q3, m02)));
            u64 r6 = fma2(q8, m02, fma2(q7, m01, mul2(q6, m00)));
            u64 r7 = fma2(q8, m12, fma2(q7, m11, mul2(q6, m01)));
            u64 r8 = fma2(q8, m22, fma2(q7, m12, mul2(q6, m02)));
            q0 = r0; q1 = r1; q2 = r2;
            q3 = r3; q4 = r4; q5 = r5;
            q6 = r6; q7 = r7; q8 = r8;
        }

        // ---- writeback: repack to consecutive pairs, 9 x STS.64 ----
        {
            u64* w8 = reinterpret_cast<u64*>(&smem[wid][buf][lane * 18]);
            w8[0] = pk2(lo2(q0), lo2(q1));
            w8[1] = pk2(lo2(q2), lo2(q3));
            w8[2] = pk2(lo2(q4), lo2(q5));
            w8[3] = pk2(lo2(q6), lo2(q7));
            w8[4] = pk2(lo2(q8), hi2(q0));
            w8[5] = pk2(hi2(q1), hi2(q2));
            w8[6] = pk2(hi2(q3), hi2(q4));
            w8[7] = pk2(hi2(q5), hi2(q6));
            w8[8] = pk2(hi2(q7), hi2(q8));
        }
        __syncwarp();

        // ---- copy out: smem -> gmem, coalesced float4 ----
        {
            const float4* s4 = reinterpret_cast<const float4*>(&smem[wid][buf][0]);
            #pragma unroll
            for (int k = 0; k < 4; k++)
                gout[lane + 32 * k] = s4[lane + 32 * k];
            if (lane < 16)
                gout[128 + lane] = s4[128 + lane];
        }
        __syncwarp();   // copy-out done before this buffer is cp.async'd again

        gin      += step / 4;   // unused after prefetch but keep consistent
        gin_next += step / 4;
        gout     += step / 4;
    }
}

extern "C" void kernel_launch(void* const* d_in, const int* in_sizes, int n_in,
                              void* d_out, int out_size)
{
    const float* x = (const float*)d_in[0];
    float* out = (float*)d_out;
    const int n_mat = in_sizes[0] / 9;          // 4,000,000
    const int n_wt  = n_mat / WMT;              // 62,500 full warp-tiles
    int grid = 152 * 4;                         // persistent, 4 CTAs/SM
    const int max_grid = (n_wt + WARPS - 1) / WARPS;
    if (grid > max_grid) grid = max_grid;
    if (grid < 1) grid = 1;
    strict_projection_kernel<<<grid, THREADS>>>(x, out, n_mat, n_wt);
}